// round 11
// baseline (speedup 1.0000x reference)
#include <cuda_runtime.h>
#include <cuda_fp16.h>
#include <cuda_bf16.h>
#include <mma.h>

using namespace nvcuda;

#define N_NODES 100000
#define N_EDGES 1600000
#define D_FEAT  64
#define UNITS   64
#define SCAN_B  1024
#define N_SCANB ((N_NODES + SCAN_B - 1) / SCAN_B)   // 98

// ---- scratch (__device__ globals; no allocations allowed) -----------------
__device__ int    g_deg[N_NODES];            // zeroed by k_gather of prior call
__device__ int    g_excl[N_NODES];
__device__ int    g_off[N_NODES + 1];
__device__ int    g_bsum[128];
__device__ float  g_inv[N_NODES];
__device__ int    g_pos[N_EDGES];            // edge's rank within its target
__device__ int    g_sorted_src[N_EDGES];
__device__ uint4  g_y4[N_NODES * 8];         // fp16 Y = (inv*x)@W : 128 B/node

// ---------------------------------------------------------------------------
// degree + per-edge rank in one atomic pass (g_deg is 0 on entry)
__global__ void k_degree(const int* __restrict__ target) {
    int e = blockIdx.x * blockDim.x + threadIdx.x;
    if (e < N_EDGES) g_pos[e] = atomicAdd(&g_deg[target[e]], 1);
}

// ---- block-local exclusive scan of degrees (shfl-based) -------------------
__global__ __launch_bounds__(SCAN_B) void k_scan1() {
    __shared__ int wsum[32];
    int tid = threadIdx.x;
    int lane = tid & 31;
    int w = tid >> 5;
    int i = blockIdx.x * SCAN_B + tid;
    int v = (i < N_NODES) ? g_deg[i] : 0;
    int s = v;
    #pragma unroll
    for (int ofs = 1; ofs < 32; ofs <<= 1) {
        int t = __shfl_up_sync(0xffffffff, s, ofs);
        if (lane >= ofs) s += t;
    }
    if (lane == 31) wsum[w] = s;
    __syncthreads();
    if (w == 0) {
        int ws = wsum[lane];
        #pragma unroll
        for (int ofs = 1; ofs < 32; ofs <<= 1) {
            int t = __shfl_up_sync(0xffffffff, ws, ofs);
            if (lane >= ofs) ws += t;
        }
        wsum[lane] = ws;   // inclusive warp sums
    }
    __syncthreads();
    int prefix = w ? wsum[w - 1] : 0;
    if (i < N_NODES) g_excl[i] = prefix + s - v;
    if (tid == 0) g_bsum[blockIdx.x] = wsum[31];
}

// ---- finish scan (per-block prefix of g_bsum) + inv -----------------------
__global__ __launch_bounds__(SCAN_B) void k_scan3() {
    __shared__ int s_add;
    int tid = threadIdx.x;
    int blk = blockIdx.x;

    if (tid < 32) {
        int acc = 0;
        for (int k = tid; k < blk; k += 32) acc += g_bsum[k];
        #pragma unroll
        for (int ofs = 16; ofs > 0; ofs >>= 1)
            acc += __shfl_down_sync(0xffffffff, acc, ofs);
        if (tid == 0) s_add = acc;
    }
    __syncthreads();
    int add = s_add;

    int i = blk * SCAN_B + tid;
    if (i < N_NODES) {
        g_off[i] = g_excl[i] + add;
        g_inv[i] = rsqrtf((float)g_deg[i]);
    }
    if (i == 0) g_off[N_NODES] = N_EDGES;
}

// ---------------------------------------------------------------------------
// Fused: blocks [0, GEMM_BLOCKS) compute Y = fp16(inv * (x@W)) via tf32 wmma;
// blocks [GEMM_BLOCKS, ...) place edges into CSR (no atomics).
// ---------------------------------------------------------------------------
#define PG_THREADS    256
#define GEMM_WARPS    8
#define ROWS_PER_BLK  (GEMM_WARPS * 16)    // 128
#define N_ROWTILES    (N_NODES / 16)       // 6250 (exact)
#define GEMM_BLOCKS   ((N_ROWTILES + GEMM_WARPS - 1) / GEMM_WARPS)   // 782
#define PLACE_BLOCKS  ((N_EDGES + PG_THREADS - 1) / PG_THREADS)      // 6250
#define PG_BLOCKS     (GEMM_BLOCKS + PLACE_BLOCKS)

__global__ __launch_bounds__(PG_THREADS) void k_place_gemm(
    const float* __restrict__ x,
    const float* __restrict__ W,
    const int*   __restrict__ source,
    const int*   __restrict__ target)
{
    __shared__ float sW[D_FEAT * UNITS];          // 16 KB
    __shared__ float sC[ROWS_PER_BLK * UNITS];    // 32 KB

    if (blockIdx.x >= GEMM_BLOCKS) {
        int e = (blockIdx.x - GEMM_BLOCKS) * PG_THREADS + threadIdx.x;
        if (e < N_EDGES)
            g_sorted_src[g_off[target[e]] + g_pos[e]] = source[e];
        return;
    }

    int tid = threadIdx.x;
    #pragma unroll
    for (int i = 0; i < (D_FEAT * UNITS) / PG_THREADS; i++)
        sW[tid + i * PG_THREADS] = W[tid + i * PG_THREADS];
    __syncthreads();

    int w = tid >> 5;
    int tile_row = blockIdx.x * GEMM_WARPS + w;
    if (tile_row < N_ROWTILES) {
        wmma::fragment<wmma::accumulator, 16, 16, 8, float> c[4];
        #pragma unroll
        for (int n = 0; n < 4; n++) wmma::fill_fragment(c[n], 0.f);

        const float* abase = x + tile_row * 16 * D_FEAT;
        #pragma unroll
        for (int k = 0; k < 8; k++) {
            wmma::fragment<wmma::matrix_a, 16, 16, 8,
                           wmma::precision::tf32, wmma::row_major> a;
            wmma::load_matrix_sync(a, abase + k * 8, D_FEAT);
            #pragma unroll
            for (int i = 0; i < a.num_elements; i++)
                a.x[i] = wmma::__float_to_tf32(a.x[i]);
            #pragma unroll
            for (int n = 0; n < 4; n++) {
                wmma::fragment<wmma::matrix_b, 16, 16, 8,
                               wmma::precision::tf32, wmma::row_major> bf;
                wmma::load_matrix_sync(bf, sW + (k * 8) * UNITS + n * 16, UNITS);
                #pragma unroll
                for (int i = 0; i < bf.num_elements; i++)
                    bf.x[i] = wmma::__float_to_tf32(bf.x[i]);
                wmma::mma_sync(c[n], a, bf, c[n]);
            }
        }
        #pragma unroll
        for (int n = 0; n < 4; n++)
            wmma::store_matrix_sync(sC + (w * 16) * UNITS + n * 16, c[n],
                                    UNITS, wmma::mem_row_major);
    }
    __syncthreads();

    // epilogue: scale rows by inv, convert to fp16, store
    int base_row = blockIdx.x * ROWS_PER_BLK;
    __half2* y2 = (__half2*)g_y4;
    #pragma unroll
    for (int i = 0; i < (ROWS_PER_BLK * UNITS / 2) / PG_THREADS; i++) {
        int idx = tid + i * PG_THREADS;      // half2 slot in block tile
        int lr  = idx >> 5;                  // local row (32 half2 per row)
        int c2  = idx & 31;
        int row = base_row + lr;
        if (row < N_NODES) {
            float s = g_inv[row];
            float2 v;
            v.x = sC[lr * UNITS + c2 * 2]     * s;
            v.y = sC[lr * UNITS + c2 * 2 + 1] * s;
            y2[row * 32 + c2] = __float22half2_rn(v);
        }
    }
}

// ---------------------------------------------------------------------------
// Gather: out[n] = relu( inv[n] * sum_{s in row(n)} Y[s] + b )
// Warp per node pair; 4 octets interleave edges with stride 4; the single
// main loop always keeps 4 independent LDG.128 per lane in flight
// (clamped indices + 0/1 FMA masks, no tail loop).
// Also re-zeroes g_deg[n] for the next graph replay.
// ---------------------------------------------------------------------------
#define GATH_THREADS   256
#define NODES_PER_GBLK 16     // 8 warps * 2 nodes

__global__ __launch_bounds__(GATH_THREADS) void k_gather(
    const float* __restrict__ b,
    float* __restrict__ out)
{
    __shared__ float sB[UNITS];
    int tid  = threadIdx.x;
    int lane = tid & 31;
    int w    = tid >> 5;
    int q    = lane >> 3;    // octet id: which edge of a group of 4
    int fl   = lane & 7;     // uint4 slot within the 128-B row

    if (tid < UNITS) sB[tid] = b[tid];
    __syncthreads();

    #pragma unroll
    for (int r = 0; r < 2; r++) {
        int n = blockIdx.x * NODES_PER_GBLK + w * 2 + r;
        if (n >= N_NODES) return;

        int beg = g_off[n];
        int end = g_off[n + 1];
        float inv_t = g_inv[n];

        float2 a0 = make_float2(0.f, 0.f), a1 = a0, a2 = a0, a3 = a0;
        float2 b0 = a0, b1 = a0, b2 = a0, b3 = a0;

        for (int ee = beg + q; ee < end; ee += 16) {
            int e1 = ee + 4, e2 = ee + 8, e3 = ee + 12;
            int s0 = g_sorted_src[ee];
            int s1 = g_sorted_src[e1 < end ? e1 : ee];
            int s2 = g_sorted_src[e2 < end ? e2 : ee];
            int s3 = g_sorted_src[e3 < end ? e3 : ee];
            float f1 = (e1 < end) ? 1.f : 0.f;
            float f2 = (e2 < end) ? 1.f : 0.f;
            float f3 = (e3 < end) ? 1.f : 0.f;
            uint4 u0 = g_y4[s0 * 8 + fl];
            uint4 u1 = g_y4[s1 * 8 + fl];
            uint4 u2 = g_y4[s2 * 8 + fl];
            uint4 u3 = g_y4[s3 * 8 + fl];
            const __half2* h0 = (const __half2*)&u0;
            const __half2* h1 = (const __half2*)&u1;
            const __half2* h2 = (const __half2*)&u2;
            const __half2* h3 = (const __half2*)&u3;
            float2 f;
            f = __half22float2(h0[0]); a0.x += f.x;            a0.y += f.y;
            f = __half22float2(h0[1]); a1.x += f.x;            a1.y += f.y;
            f = __half22float2(h0[2]); a2.x += f.x;            a2.y += f.y;
            f = __half22float2(h0[3]); a3.x += f.x;            a3.y += f.y;
            f = __half22float2(h1[0]); b0.x = fmaf(f1, f.x, b0.x); b0.y = fmaf(f1, f.y, b0.y);
            f = __half22float2(h1[1]); b1.x = fmaf(f1, f.x, b1.x); b1.y = fmaf(f1, f.y, b1.y);
            f = __half22float2(h1[2]); b2.x = fmaf(f1, f.x, b2.x); b2.y = fmaf(f1, f.y, b2.y);
            f = __half22float2(h1[3]); b3.x = fmaf(f1, f.x, b3.x); b3.y = fmaf(f1, f.y, b3.y);
            f = __half22float2(h2[0]); a0.x = fmaf(f2, f.x, a0.x); a0.y = fmaf(f2, f.y, a0.y);
            f = __half22float2(h2[1]); a1.x = fmaf(f2, f.x, a1.x); a1.y = fmaf(f2, f.y, a1.y);
            f = __half22float2(h2[2]); a2.x = fmaf(f2, f.x, a2.x); a2.y = fmaf(f2, f.y, a2.y);
            f = __half22float2(h2[3]); a3.x = fmaf(f2, f.x, a3.x); a3.y = fmaf(f2, f.y, a3.y);
            f = __half22float2(h3[0]); b0.x = fmaf(f3, f.x, b0.x); b0.y = fmaf(f3, f.y, b0.y);
            f = __half22float2(h3[1]); b1.x = fmaf(f3, f.x, b1.x); b1.y = fmaf(f3, f.y, b1.y);
            f = __half22float2(h3[2]); b2.x = fmaf(f3, f.x, b2.x); b2.y = fmaf(f3, f.y, b2.y);
            f = __half22float2(h3[3]); b3.x = fmaf(f3, f.x, b3.x); b3.y = fmaf(f3, f.y, b3.y);
        }

        a0.x += b0.x; a0.y += b0.y;  a1.x += b1.x; a1.y += b1.y;
        a2.x += b2.x; a2.y += b2.y;  a3.x += b3.x; a3.y += b3.y;

        // combine octets: lanes 0-7 end with full sums for cols fl*8..+7
        #pragma unroll
        for (int ofs = 16; ofs >= 8; ofs >>= 1) {
            a0.x += __shfl_down_sync(0xffffffff, a0.x, ofs);
            a0.y += __shfl_down_sync(0xffffffff, a0.y, ofs);
            a1.x += __shfl_down_sync(0xffffffff, a1.x, ofs);
            a1.y += __shfl_down_sync(0xffffffff, a1.y, ofs);
            a2.x += __shfl_down_sync(0xffffffff, a2.x, ofs);
            a2.y += __shfl_down_sync(0xffffffff, a2.y, ofs);
            a3.x += __shfl_down_sync(0xffffffff, a3.x, ofs);
            a3.y += __shfl_down_sync(0xffffffff, a3.y, ofs);
        }
        if (q == 0) {
            int cb = fl * 8;
            float4 o0, o1;
            o0.x = fmaxf(fmaf(inv_t, a0.x, sB[cb + 0]), 0.f);
            o0.y = fmaxf(fmaf(inv_t, a0.y, sB[cb + 1]), 0.f);
            o0.z = fmaxf(fmaf(inv_t, a1.x, sB[cb + 2]), 0.f);
            o0.w = fmaxf(fmaf(inv_t, a1.y, sB[cb + 3]), 0.f);
            o1.x = fmaxf(fmaf(inv_t, a2.x, sB[cb + 4]), 0.f);
            o1.y = fmaxf(fmaf(inv_t, a2.y, sB[cb + 5]), 0.f);
            o1.z = fmaxf(fmaf(inv_t, a3.x, sB[cb + 6]), 0.f);
            o1.w = fmaxf(fmaf(inv_t, a3.y, sB[cb + 7]), 0.f);
            float4* out4 = (float4*)(out + n * UNITS);
            out4[fl * 2]     = o0;
            out4[fl * 2 + 1] = o1;
        }
        if (lane == 0) g_deg[n] = 0;   // reset for next replay
        __syncwarp();
    }
}

// ---------------------------------------------------------------------------
extern "C" void kernel_launch(void* const* d_in, const int* in_sizes, int n_in,
                              void* d_out, int out_size) {
    const float* x      = (const float*)d_in[0];
    const float* W      = (const float*)d_in[1];
    const float* b      = (const float*)d_in[2];
    const int*   source = (const int*)d_in[3];
    const int*   target = (const int*)d_in[4];
    float* out = (float*)d_out;

    const int T = 256;
    k_degree<<<(N_EDGES + T - 1) / T, T>>>(target);
    k_scan1<<<N_SCANB, SCAN_B>>>();
    k_scan3<<<N_SCANB, SCAN_B>>>();
    k_place_gemm<<<PG_BLOCKS, PG_THREADS>>>(x, W, source, target);
    k_gather<<<(N_NODES + NODES_PER_GBLK - 1) / NODES_PER_GBLK, GATH_THREADS>>>(b, out);
}

// round 12
// speedup vs baseline: 1.2374x; 1.2374x over previous
#include <cuda_runtime.h>
#include <cuda_fp16.h>
#include <cuda_bf16.h>
#include <mma.h>

using namespace nvcuda;

#define N_NODES 100000
#define N_EDGES 1600000
#define D_FEAT  64
#define UNITS   64
#define SCAN_B  1024
#define N_SCANB ((N_NODES + SCAN_B - 1) / SCAN_B)   // 98

// ---- scratch (__device__ globals; no allocations allowed) -----------------
__device__ int    g_deg[N_NODES];            // zeroed by k_gather of prior call
__device__ int    g_excl[N_NODES];
__device__ int    g_off[N_NODES + 1];
__device__ int    g_bsum[128];
__device__ float  g_inv[N_NODES];
__device__ int    g_pos[N_EDGES];            // edge's rank within its target
__device__ int    g_sorted_src[N_EDGES];
__device__ uint4  g_y4[N_NODES * 8];         // fp16 Y = (inv*x)@W : 128 B/node

// ---------------------------------------------------------------------------
// degree + per-edge rank in one atomic pass (g_deg is 0 on entry)
__global__ void k_degree(const int* __restrict__ target) {
    int e = blockIdx.x * blockDim.x + threadIdx.x;
    if (e < N_EDGES) g_pos[e] = atomicAdd(&g_deg[target[e]], 1);
}

// ---- block-local exclusive scan of degrees (shfl-based) -------------------
__global__ __launch_bounds__(SCAN_B) void k_scan1() {
    __shared__ int wsum[32];
    int tid = threadIdx.x;
    int lane = tid & 31;
    int w = tid >> 5;
    int i = blockIdx.x * SCAN_B + tid;
    int v = (i < N_NODES) ? g_deg[i] : 0;
    int s = v;
    #pragma unroll
    for (int ofs = 1; ofs < 32; ofs <<= 1) {
        int t = __shfl_up_sync(0xffffffff, s, ofs);
        if (lane >= ofs) s += t;
    }
    if (lane == 31) wsum[w] = s;
    __syncthreads();
    if (w == 0) {
        int ws = wsum[lane];
        #pragma unroll
        for (int ofs = 1; ofs < 32; ofs <<= 1) {
            int t = __shfl_up_sync(0xffffffff, ws, ofs);
            if (lane >= ofs) ws += t;
        }
        wsum[lane] = ws;   // inclusive warp sums
    }
    __syncthreads();
    int prefix = w ? wsum[w - 1] : 0;
    if (i < N_NODES) g_excl[i] = prefix + s - v;
    if (tid == 0) g_bsum[blockIdx.x] = wsum[31];
}

// ---- finish scan (per-block prefix of g_bsum) + inv -----------------------
__global__ __launch_bounds__(SCAN_B) void k_scan3() {
    __shared__ int s_add;
    int tid = threadIdx.x;
    int blk = blockIdx.x;

    if (tid < 32) {
        int acc = 0;
        for (int k = tid; k < blk; k += 32) acc += g_bsum[k];
        #pragma unroll
        for (int ofs = 16; ofs > 0; ofs >>= 1)
            acc += __shfl_down_sync(0xffffffff, acc, ofs);
        if (tid == 0) s_add = acc;
    }
    __syncthreads();
    int add = s_add;

    int i = blk * SCAN_B + tid;
    if (i < N_NODES) {
        g_off[i] = g_excl[i] + add;
        g_inv[i] = rsqrtf((float)g_deg[i]);
    }
    if (i == 0) g_off[N_NODES] = N_EDGES;
}

// ---- place edges into CSR (no atomics, featherweight) ---------------------
__global__ void k_place(const int* __restrict__ source,
                        const int* __restrict__ target) {
    int e = blockIdx.x * blockDim.x + threadIdx.x;
    if (e >= N_EDGES) return;
    g_sorted_src[g_off[target[e]] + g_pos[e]] = source[e];
}

// ---------------------------------------------------------------------------
// Dense GEMM: Y[n,:] = fp16( inv[n] * (x[n,:] @ W) )  via tf32 wmma.
// ---------------------------------------------------------------------------
#define GEMM_THREADS  256
#define GEMM_WARPS    8
#define ROWS_PER_BLK  (GEMM_WARPS * 16)    // 128
#define N_ROWTILES    (N_NODES / 16)       // 6250 (exact)
#define GEMM_BLOCKS   ((N_ROWTILES + GEMM_WARPS - 1) / GEMM_WARPS)   // 782

__global__ __launch_bounds__(GEMM_THREADS) void k_gemm(
    const float* __restrict__ x,
    const float* __restrict__ W)
{
    __shared__ float sW[D_FEAT * UNITS];          // 16 KB
    __shared__ float sC[ROWS_PER_BLK * UNITS];    // 32 KB

    int tid = threadIdx.x;
    #pragma unroll
    for (int i = 0; i < (D_FEAT * UNITS) / GEMM_THREADS; i++)
        sW[tid + i * GEMM_THREADS] = W[tid + i * GEMM_THREADS];
    __syncthreads();

    int w = tid >> 5;
    int tile_row = blockIdx.x * GEMM_WARPS + w;
    if (tile_row < N_ROWTILES) {
        wmma::fragment<wmma::accumulator, 16, 16, 8, float> c[4];
        #pragma unroll
        for (int n = 0; n < 4; n++) wmma::fill_fragment(c[n], 0.f);

        const float* abase = x + tile_row * 16 * D_FEAT;
        #pragma unroll
        for (int k = 0; k < 8; k++) {
            wmma::fragment<wmma::matrix_a, 16, 16, 8,
                           wmma::precision::tf32, wmma::row_major> a;
            wmma::load_matrix_sync(a, abase + k * 8, D_FEAT);
            #pragma unroll
            for (int i = 0; i < a.num_elements; i++)
                a.x[i] = wmma::__float_to_tf32(a.x[i]);
            #pragma unroll
            for (int n = 0; n < 4; n++) {
                wmma::fragment<wmma::matrix_b, 16, 16, 8,
                               wmma::precision::tf32, wmma::row_major> bf;
                wmma::load_matrix_sync(bf, sW + (k * 8) * UNITS + n * 16, UNITS);
                #pragma unroll
                for (int i = 0; i < bf.num_elements; i++)
                    bf.x[i] = wmma::__float_to_tf32(bf.x[i]);
                wmma::mma_sync(c[n], a, bf, c[n]);
            }
        }
        #pragma unroll
        for (int n = 0; n < 4; n++)
            wmma::store_matrix_sync(sC + (w * 16) * UNITS + n * 16, c[n],
                                    UNITS, wmma::mem_row_major);
    }
    __syncthreads();

    // epilogue: scale rows by inv, convert to fp16, store
    int base_row = blockIdx.x * ROWS_PER_BLK;
    __half2* y2 = (__half2*)g_y4;
    #pragma unroll
    for (int i = 0; i < (ROWS_PER_BLK * UNITS / 2) / GEMM_THREADS; i++) {
        int idx = tid + i * GEMM_THREADS;    // half2 slot in block tile
        int lr  = idx >> 5;                  // local row (32 half2 per row)
        int c2  = idx & 31;
        int row = base_row + lr;
        if (row < N_NODES) {
            float s = g_inv[row];
            float2 v;
            v.x = sC[lr * UNITS + c2 * 2]     * s;
            v.y = sC[lr * UNITS + c2 * 2 + 1] * s;
            y2[row * 32 + c2] = __float22half2_rn(v);
        }
    }
}

// ---------------------------------------------------------------------------
// Gather: out[n] = relu( inv[n] * sum_{s in row(n)} Y[s] + b )
// Warp per node pair; 4 octets interleave edges with stride 4; the single
// main loop always keeps 4 independent LDG.128 per lane in flight
// (clamped indices + 0/1 FMA masks, no tail loop).
// Also re-zeroes g_deg[n] for the next graph replay.
// ---------------------------------------------------------------------------
#define GATH_THREADS   256
#define NODES_PER_GBLK 16     // 8 warps * 2 nodes

__global__ __launch_bounds__(GATH_THREADS) void k_gather(
    const float* __restrict__ b,
    float* __restrict__ out)
{
    __shared__ float sB[UNITS];
    int tid  = threadIdx.x;
    int lane = tid & 31;
    int w    = tid >> 5;
    int q    = lane >> 3;    // octet id: which edge of a group of 4
    int fl   = lane & 7;     // uint4 slot within the 128-B row

    if (tid < UNITS) sB[tid] = b[tid];
    __syncthreads();

    #pragma unroll
    for (int r = 0; r < 2; r++) {
        int n = blockIdx.x * NODES_PER_GBLK + w * 2 + r;
        if (n >= N_NODES) return;

        int beg = g_off[n];
        int end = g_off[n + 1];
        float inv_t = g_inv[n];

        float2 a0 = make_float2(0.f, 0.f), a1 = a0, a2 = a0, a3 = a0;
        float2 b0 = a0, b1 = a0, b2 = a0, b3 = a0;

        for (int ee = beg + q; ee < end; ee += 16) {
            int e1 = ee + 4, e2 = ee + 8, e3 = ee + 12;
            int s0 = g_sorted_src[ee];
            int s1 = g_sorted_src[e1 < end ? e1 : ee];
            int s2 = g_sorted_src[e2 < end ? e2 : ee];
            int s3 = g_sorted_src[e3 < end ? e3 : ee];
            float f1 = (e1 < end) ? 1.f : 0.f;
            float f2 = (e2 < end) ? 1.f : 0.f;
            float f3 = (e3 < end) ? 1.f : 0.f;
            uint4 u0 = g_y4[s0 * 8 + fl];
            uint4 u1 = g_y4[s1 * 8 + fl];
            uint4 u2 = g_y4[s2 * 8 + fl];
            uint4 u3 = g_y4[s3 * 8 + fl];
            const __half2* h0 = (const __half2*)&u0;
            const __half2* h1 = (const __half2*)&u1;
            const __half2* h2 = (const __half2*)&u2;
            const __half2* h3 = (const __half2*)&u3;
            float2 f;
            f = __half22float2(h0[0]); a0.x += f.x;            a0.y += f.y;
            f = __half22float2(h0[1]); a1.x += f.x;            a1.y += f.y;
            f = __half22float2(h0[2]); a2.x += f.x;            a2.y += f.y;
            f = __half22float2(h0[3]); a3.x += f.x;            a3.y += f.y;
            f = __half22float2(h1[0]); b0.x = fmaf(f1, f.x, b0.x); b0.y = fmaf(f1, f.y, b0.y);
            f = __half22float2(h1[1]); b1.x = fmaf(f1, f.x, b1.x); b1.y = fmaf(f1, f.y, b1.y);
            f = __half22float2(h1[2]); b2.x = fmaf(f1, f.x, b2.x); b2.y = fmaf(f1, f.y, b2.y);
            f = __half22float2(h1[3]); b3.x = fmaf(f1, f.x, b3.x); b3.y = fmaf(f1, f.y, b3.y);
            f = __half22float2(h2[0]); a0.x = fmaf(f2, f.x, a0.x); a0.y = fmaf(f2, f.y, a0.y);
            f = __half22float2(h2[1]); a1.x = fmaf(f2, f.x, a1.x); a1.y = fmaf(f2, f.y, a1.y);
            f = __half22float2(h2[2]); a2.x = fmaf(f2, f.x, a2.x); a2.y = fmaf(f2, f.y, a2.y);
            f = __half22float2(h2[3]); a3.x = fmaf(f2, f.x, a3.x); a3.y = fmaf(f2, f.y, a3.y);
            f = __half22float2(h3[0]); b0.x = fmaf(f3, f.x, b0.x); b0.y = fmaf(f3, f.y, b0.y);
            f = __half22float2(h3[1]); b1.x = fmaf(f3, f.x, b1.x); b1.y = fmaf(f3, f.y, b1.y);
            f = __half22float2(h3[2]); b2.x = fmaf(f3, f.x, b2.x); b2.y = fmaf(f3, f.y, b2.y);
            f = __half22float2(h3[3]); b3.x = fmaf(f3, f.x, b3.x); b3.y = fmaf(f3, f.y, b3.y);
        }

        a0.x += b0.x; a0.y += b0.y;  a1.x += b1.x; a1.y += b1.y;
        a2.x += b2.x; a2.y += b2.y;  a3.x += b3.x; a3.y += b3.y;

        // combine octets: lanes 0-7 end with full sums for cols fl*8..+7
        #pragma unroll
        for (int ofs = 16; ofs >= 8; ofs >>= 1) {
            a0.x += __shfl_down_sync(0xffffffff, a0.x, ofs);
            a0.y += __shfl_down_sync(0xffffffff, a0.y, ofs);
            a1.x += __shfl_down_sync(0xffffffff, a1.x, ofs);
            a1.y += __shfl_down_sync(0xffffffff, a1.y, ofs);
            a2.x += __shfl_down_sync(0xffffffff, a2.x, ofs);
            a2.y += __shfl_down_sync(0xffffffff, a2.y, ofs);
            a3.x += __shfl_down_sync(0xffffffff, a3.x, ofs);
            a3.y += __shfl_down_sync(0xffffffff, a3.y, ofs);
        }
        if (q == 0) {
            int cb = fl * 8;
            float4 o0, o1;
            o0.x = fmaxf(fmaf(inv_t, a0.x, sB[cb + 0]), 0.f);
            o0.y = fmaxf(fmaf(inv_t, a0.y, sB[cb + 1]), 0.f);
            o0.z = fmaxf(fmaf(inv_t, a1.x, sB[cb + 2]), 0.f);
            o0.w = fmaxf(fmaf(inv_t, a1.y, sB[cb + 3]), 0.f);
            o1.x = fmaxf(fmaf(inv_t, a2.x, sB[cb + 4]), 0.f);
            o1.y = fmaxf(fmaf(inv_t, a2.y, sB[cb + 5]), 0.f);
            o1.z = fmaxf(fmaf(inv_t, a3.x, sB[cb + 6]), 0.f);
            o1.w = fmaxf(fmaf(inv_t, a3.y, sB[cb + 7]), 0.f);
            float4* out4 = (float4*)(out + n * UNITS);
            out4[fl * 2]     = o0;
            out4[fl * 2 + 1] = o1;
        }
        if (lane == 0) g_deg[n] = 0;   // reset for next replay
        __syncwarp();
    }
}

// ---------------------------------------------------------------------------
extern "C" void kernel_launch(void* const* d_in, const int* in_sizes, int n_in,
                              void* d_out, int out_size) {
    const float* x      = (const float*)d_in[0];
    const float* W      = (const float*)d_in[1];
    const float* b      = (const float*)d_in[2];
    const int*   source = (const int*)d_in[3];
    const int*   target = (const int*)d_in[4];
    float* out = (float*)d_out;

    const int T = 256;
    k_degree<<<(N_EDGES + T - 1) / T, T>>>(target);
    k_scan1<<<N_SCANB, SCAN_B>>>();
    k_scan3<<<N_SCANB, SCAN_B>>>();
    k_place<<<(N_EDGES + T - 1) / T, T>>>(source, target);
    k_gemm<<<GEMM_BLOCKS, GEMM_THREADS>>>(x, W);
    k_gather<<<(N_NODES + NODES_PER_GBLK - 1) / NODES_PER_GBLK, GATH_THREADS>>>(b, out);
}

// round 13
// speedup vs baseline: 1.3267x; 1.0721x over previous
#include <cuda_runtime.h>
#include <cuda_fp16.h>
#include <cuda_bf16.h>
#include <mma.h>

using namespace nvcuda;

#define N_NODES 100000
#define N_EDGES 1600000
#define D_FEAT  64
#define UNITS   64
#define SCAN_B  1024
#define N_SCANB ((N_NODES + SCAN_B - 1) / SCAN_B)   // 98

// ---- scratch (__device__ globals; no allocations allowed) -----------------
__device__ int    g_deg[N_NODES];            // zeroed by k_gather of prior call
__device__ int    g_excl[N_NODES];
__device__ int    g_off[N_NODES + 1];
__device__ int    g_bsum[128];
__device__ float  g_inv[N_NODES];
__device__ int    g_tp[N_EDGES];             // packed (pos<<17)|target
__device__ int    g_sorted_src[N_EDGES];
__device__ uint4  g_y4[N_NODES * 8];         // fp16 Y = (inv*x)@W : 128 B/node

// ---------------------------------------------------------------------------
// degree + per-edge rank in one atomic pass (g_deg is 0 on entry)
__global__ void k_degree(const int* __restrict__ target) {
    int e = blockIdx.x * blockDim.x + threadIdx.x;
    if (e < N_EDGES) {
        int t = target[e];
        int pos = atomicAdd(&g_deg[t], 1);
        g_tp[e] = (pos << 17) | t;
    }
}

// ---- block-local exclusive scan of degrees (shfl-based) -------------------
__global__ __launch_bounds__(SCAN_B) void k_scan1() {
    __shared__ int wsum[32];
    int tid = threadIdx.x;
    int lane = tid & 31;
    int w = tid >> 5;
    int i = blockIdx.x * SCAN_B + tid;
    int v = (i < N_NODES) ? g_deg[i] : 0;
    int s = v;
    #pragma unroll
    for (int ofs = 1; ofs < 32; ofs <<= 1) {
        int t = __shfl_up_sync(0xffffffff, s, ofs);
        if (lane >= ofs) s += t;
    }
    if (lane == 31) wsum[w] = s;
    __syncthreads();
    if (w == 0) {
        int ws = wsum[lane];
        #pragma unroll
        for (int ofs = 1; ofs < 32; ofs <<= 1) {
            int t = __shfl_up_sync(0xffffffff, ws, ofs);
            if (lane >= ofs) ws += t;
        }
        wsum[lane] = ws;   // inclusive warp sums
    }
    __syncthreads();
    int prefix = w ? wsum[w - 1] : 0;
    if (i < N_NODES) g_excl[i] = prefix + s - v;
    if (tid == 0) g_bsum[blockIdx.x] = wsum[31];
}

// ---- finish scan (per-block prefix of g_bsum) + inv -----------------------
__global__ __launch_bounds__(SCAN_B) void k_scan3() {
    __shared__ int s_add;
    int tid = threadIdx.x;
    int blk = blockIdx.x;

    if (tid < 32) {
        int acc = 0;
        for (int k = tid; k < blk; k += 32) acc += g_bsum[k];
        #pragma unroll
        for (int ofs = 16; ofs > 0; ofs >>= 1)
            acc += __shfl_down_sync(0xffffffff, acc, ofs);
        if (tid == 0) s_add = acc;
    }
    __syncthreads();
    int add = s_add;

    int i = blk * SCAN_B + tid;
    if (i < N_NODES) {
        g_off[i] = g_excl[i] + add;
        g_inv[i] = rsqrtf((float)g_deg[i]);
    }
    if (i == 0) g_off[N_NODES] = N_EDGES;
}

// ---- place edges into CSR (no atomics, one packed read) -------------------
__global__ void k_place(const int* __restrict__ source) {
    int e = blockIdx.x * blockDim.x + threadIdx.x;
    if (e >= N_EDGES) return;
    int tp = g_tp[e];
    int t = tp & 0x1FFFF;
    int pos = tp >> 17;
    g_sorted_src[g_off[t] + pos] = source[e];
}

// ---------------------------------------------------------------------------
// Dense GEMM: Y[n,:] = fp16( inv[n] * (x[n,:] @ W) )  via tf32 wmma.
// ---------------------------------------------------------------------------
#define GEMM_THREADS  256
#define GEMM_WARPS    8
#define ROWS_PER_BLK  (GEMM_WARPS * 16)    // 128
#define N_ROWTILES    (N_NODES / 16)       // 6250 (exact)
#define GEMM_BLOCKS   ((N_ROWTILES + GEMM_WARPS - 1) / GEMM_WARPS)   // 782

__global__ __launch_bounds__(GEMM_THREADS) void k_gemm(
    const float* __restrict__ x,
    const float* __restrict__ W)
{
    __shared__ float sW[D_FEAT * UNITS];          // 16 KB
    __shared__ float sC[ROWS_PER_BLK * UNITS];    // 32 KB

    int tid = threadIdx.x;
    #pragma unroll
    for (int i = 0; i < (D_FEAT * UNITS) / GEMM_THREADS; i++)
        sW[tid + i * GEMM_THREADS] = W[tid + i * GEMM_THREADS];
    __syncthreads();

    int w = tid >> 5;
    int tile_row = blockIdx.x * GEMM_WARPS + w;
    if (tile_row < N_ROWTILES) {
        wmma::fragment<wmma::accumulator, 16, 16, 8, float> c[4];
        #pragma unroll
        for (int n = 0; n < 4; n++) wmma::fill_fragment(c[n], 0.f);

        const float* abase = x + tile_row * 16 * D_FEAT;
        #pragma unroll
        for (int k = 0; k < 8; k++) {
            wmma::fragment<wmma::matrix_a, 16, 16, 8,
                           wmma::precision::tf32, wmma::row_major> a;
            wmma::load_matrix_sync(a, abase + k * 8, D_FEAT);
            #pragma unroll
            for (int i = 0; i < a.num_elements; i++)
                a.x[i] = wmma::__float_to_tf32(a.x[i]);
            #pragma unroll
            for (int n = 0; n < 4; n++) {
                wmma::fragment<wmma::matrix_b, 16, 16, 8,
                               wmma::precision::tf32, wmma::row_major> bf;
                wmma::load_matrix_sync(bf, sW + (k * 8) * UNITS + n * 16, UNITS);
                #pragma unroll
                for (int i = 0; i < bf.num_elements; i++)
                    bf.x[i] = wmma::__float_to_tf32(bf.x[i]);
                wmma::mma_sync(c[n], a, bf, c[n]);
            }
        }
        #pragma unroll
        for (int n = 0; n < 4; n++)
            wmma::store_matrix_sync(sC + (w * 16) * UNITS + n * 16, c[n],
                                    UNITS, wmma::mem_row_major);
    }
    __syncthreads();

    // epilogue: scale rows by inv, convert to fp16, store
    int base_row = blockIdx.x * ROWS_PER_BLK;
    __half2* y2 = (__half2*)g_y4;
    #pragma unroll
    for (int i = 0; i < (ROWS_PER_BLK * UNITS / 2) / GEMM_THREADS; i++) {
        int idx = tid + i * GEMM_THREADS;    // half2 slot in block tile
        int lr  = idx >> 5;                  // local row (32 half2 per row)
        int c2  = idx & 31;
        int row = base_row + lr;
        if (row < N_NODES) {
            float s = g_inv[row];
            float2 v;
            v.x = sC[lr * UNITS + c2 * 2]     * s;
            v.y = sC[lr * UNITS + c2 * 2 + 1] * s;
            y2[row * 32 + c2] = __float22half2_rn(v);
        }
    }
}

// ---------------------------------------------------------------------------
// Gather: out[n] = relu( inv[n] * sum_{s in row(n)} Y[s] + b )
// One node per warp; 4 octets interleave edges with stride 4; the single
// main loop keeps 4 independent LDG.128 per lane in flight.
// Also re-zeroes g_deg[n] for the next graph replay.
// ---------------------------------------------------------------------------
#define GATH_THREADS   256
#define NODES_PER_GBLK 8      // 8 warps * 1 node

__global__ __launch_bounds__(GATH_THREADS) void k_gather(
    const float* __restrict__ b,
    float* __restrict__ out)
{
    __shared__ float sB[UNITS];
    int tid  = threadIdx.x;
    int lane = tid & 31;
    int w    = tid >> 5;
    int q    = lane >> 3;    // octet id: which edge of a group of 4
    int fl   = lane & 7;     // uint4 slot within the 128-B row

    if (tid < UNITS) sB[tid] = b[tid];
    __syncthreads();

    int n = blockIdx.x * NODES_PER_GBLK + w;
    if (n >= N_NODES) return;

    int beg = g_off[n];
    int end = g_off[n + 1];
    float inv_t = g_inv[n];

    float2 a0 = make_float2(0.f, 0.f), a1 = a0, a2 = a0, a3 = a0;
    float2 b0 = a0, b1 = a0, b2 = a0, b3 = a0;

    for (int ee = beg + q; ee < end; ee += 16) {
        int e1 = ee + 4, e2 = ee + 8, e3 = ee + 12;
        int s0 = g_sorted_src[ee];
        int s1 = g_sorted_src[e1 < end ? e1 : ee];
        int s2 = g_sorted_src[e2 < end ? e2 : ee];
        int s3 = g_sorted_src[e3 < end ? e3 : ee];
        float f1 = (e1 < end) ? 1.f : 0.f;
        float f2 = (e2 < end) ? 1.f : 0.f;
        float f3 = (e3 < end) ? 1.f : 0.f;
        uint4 u0 = g_y4[s0 * 8 + fl];
        uint4 u1 = g_y4[s1 * 8 + fl];
        uint4 u2 = g_y4[s2 * 8 + fl];
        uint4 u3 = g_y4[s3 * 8 + fl];
        const __half2* h0 = (const __half2*)&u0;
        const __half2* h1 = (const __half2*)&u1;
        const __half2* h2 = (const __half2*)&u2;
        const __half2* h3 = (const __half2*)&u3;
        float2 f;
        f = __half22float2(h0[0]); a0.x += f.x;            a0.y += f.y;
        f = __half22float2(h0[1]); a1.x += f.x;            a1.y += f.y;
        f = __half22float2(h0[2]); a2.x += f.x;            a2.y += f.y;
        f = __half22float2(h0[3]); a3.x += f.x;            a3.y += f.y;
        f = __half22float2(h1[0]); b0.x = fmaf(f1, f.x, b0.x); b0.y = fmaf(f1, f.y, b0.y);
        f = __half22float2(h1[1]); b1.x = fmaf(f1, f.x, b1.x); b1.y = fmaf(f1, f.y, b1.y);
        f = __half22float2(h1[2]); b2.x = fmaf(f1, f.x, b2.x); b2.y = fmaf(f1, f.y, b2.y);
        f = __half22float2(h1[3]); b3.x = fmaf(f1, f.x, b3.x); b3.y = fmaf(f1, f.y, b3.y);
        f = __half22float2(h2[0]); a0.x = fmaf(f2, f.x, a0.x); a0.y = fmaf(f2, f.y, a0.y);
        f = __half22float2(h2[1]); a1.x = fmaf(f2, f.x, a1.x); a1.y = fmaf(f2, f.y, a1.y);
        f = __half22float2(h2[2]); a2.x = fmaf(f2, f.x, a2.x); a2.y = fmaf(f2, f.y, a2.y);
        f = __half22float2(h2[3]); a3.x = fmaf(f2, f.x, a3.x); a3.y = fmaf(f2, f.y, a3.y);
        f = __half22float2(h3[0]); b0.x = fmaf(f3, f.x, b0.x); b0.y = fmaf(f3, f.y, b0.y);
        f = __half22float2(h3[1]); b1.x = fmaf(f3, f.x, b1.x); b1.y = fmaf(f3, f.y, b1.y);
        f = __half22float2(h3[2]); b2.x = fmaf(f3, f.x, b2.x); b2.y = fmaf(f3, f.y, b2.y);
        f = __half22float2(h3[3]); b3.x = fmaf(f3, f.x, b3.x); b3.y = fmaf(f3, f.y, b3.y);
    }

    a0.x += b0.x; a0.y += b0.y;  a1.x += b1.x; a1.y += b1.y;
    a2.x += b2.x; a2.y += b2.y;  a3.x += b3.x; a3.y += b3.y;

    // combine octets: lanes 0-7 end with full sums for cols fl*8..+7
    #pragma unroll
    for (int ofs = 16; ofs >= 8; ofs >>= 1) {
        a0.x += __shfl_down_sync(0xffffffff, a0.x, ofs);
        a0.y += __shfl_down_sync(0xffffffff, a0.y, ofs);
        a1.x += __shfl_down_sync(0xffffffff, a1.x, ofs);
        a1.y += __shfl_down_sync(0xffffffff, a1.y, ofs);
        a2.x += __shfl_down_sync(0xffffffff, a2.x, ofs);
        a2.y += __shfl_down_sync(0xffffffff, a2.y, ofs);
        a3.x += __shfl_down_sync(0xffffffff, a3.x, ofs);
        a3.y += __shfl_down_sync(0xffffffff, a3.y, ofs);
    }
    if (q == 0) {
        int cb = fl * 8;
        float4 o0, o1;
        o0.x = fmaxf(fmaf(inv_t, a0.x, sB[cb + 0]), 0.f);
        o0.y = fmaxf(fmaf(inv_t, a0.y, sB[cb + 1]), 0.f);
        o0.z = fmaxf(fmaf(inv_t, a1.x, sB[cb + 2]), 0.f);
        o0.w = fmaxf(fmaf(inv_t, a1.y, sB[cb + 3]), 0.f);
        o1.x = fmaxf(fmaf(inv_t, a2.x, sB[cb + 4]), 0.f);
        o1.y = fmaxf(fmaf(inv_t, a2.y, sB[cb + 5]), 0.f);
        o1.z = fmaxf(fmaf(inv_t, a3.x, sB[cb + 6]), 0.f);
        o1.w = fmaxf(fmaf(inv_t, a3.y, sB[cb + 7]), 0.f);
        float4* out4 = (float4*)(out + n * UNITS);
        out4[fl * 2]     = o0;
        out4[fl * 2 + 1] = o1;
    }
    if (lane == 0) g_deg[n] = 0;   // reset for next replay
}

// ---------------------------------------------------------------------------
extern "C" void kernel_launch(void* const* d_in, const int* in_sizes, int n_in,
                              void* d_out, int out_size) {
    const float* x      = (const float*)d_in[0];
    const float* W      = (const float*)d_in[1];
    const float* b      = (const float*)d_in[2];
    const int*   source = (const int*)d_in[3];
    const int*   target = (const int*)d_in[4];
    float* out = (float*)d_out;

    // side stream + events for the place ∥ gemm fork (created once; the
    // launch sequence below is identical on every call)
    static cudaStream_t s1 = nullptr;
    static cudaEvent_t evA = nullptr, evB = nullptr;
    if (s1 == nullptr) {
        cudaStreamCreateWithFlags(&s1, cudaStreamNonBlocking);
        cudaEventCreateWithFlags(&evA, cudaEventDisableTiming);
        cudaEventCreateWithFlags(&evB, cudaEventDisableTiming);
    }

    const int T = 256;
    k_degree<<<(N_EDGES + T - 1) / T, T>>>(target);
    k_scan1<<<N_SCANB, SCAN_B>>>();
    k_scan3<<<N_SCANB, SCAN_B>>>();

    // fork: gemm (needs only g_inv) runs concurrently with place
    cudaEventRecord(evA, 0);
    cudaStreamWaitEvent(s1, evA, 0);
    k_gemm<<<GEMM_BLOCKS, GEMM_THREADS, 0, s1>>>(x, W);
    cudaEventRecord(evB, s1);

    k_place<<<(N_EDGES + T - 1) / T, T>>>(source);

    // join: gather needs both place (stream 0) and gemm (s1)
    cudaStreamWaitEvent(0, evB, 0);
    k_gather<<<(N_NODES + NODES_PER_GBLK - 1) / NODES_PER_GBLK, GATH_THREADS>>>(b, out);
}

// round 14
// speedup vs baseline: 1.3439x; 1.0130x over previous
#include <cuda_runtime.h>
#include <cuda_fp16.h>
#include <cuda_bf16.h>
#include <mma.h>

using namespace nvcuda;

#define N_NODES 100000
#define N_EDGES 1600000
#define D_FEAT  64
#define UNITS   64
#define SCAN_B  1024
#define N_SCANB ((N_NODES + SCAN_B - 1) / SCAN_B)   // 98

// ---- scratch (__device__ globals; no allocations allowed) -----------------
__device__ int    g_deg[N_NODES];            // zeroed by k_gather of prior call
__device__ int    g_excl[N_NODES];
__device__ int    g_off[N_NODES + 1];
__device__ int    g_bsum[128];
__device__ float  g_inv[N_NODES];
__device__ int    g_tp[N_EDGES];             // packed (pos<<17)|target
__device__ int    g_sorted_src[N_EDGES];
__device__ uint4  g_y4[N_NODES * 8];         // fp16 Y = (inv*x)@W : 128 B/node

// ---------------------------------------------------------------------------
// degree + per-edge rank in one atomic pass (g_deg is 0 on entry)
__global__ void k_degree(const int* __restrict__ target) {
    int e = blockIdx.x * blockDim.x + threadIdx.x;
    if (e < N_EDGES) {
        int t = target[e];
        int pos = atomicAdd(&g_deg[t], 1);
        g_tp[e] = (pos << 17) | t;
    }
}

// ---- inv = rsqrt(deg): tiny kernel so gemm can fork immediately after -----
__global__ void k_inv() {
    int i = blockIdx.x * blockDim.x + threadIdx.x;
    if (i < N_NODES) g_inv[i] = rsqrtf((float)g_deg[i]);
}

// ---- block-local exclusive scan of degrees (shfl-based) -------------------
__global__ __launch_bounds__(SCAN_B) void k_scan1() {
    __shared__ int wsum[32];
    int tid = threadIdx.x;
    int lane = tid & 31;
    int w = tid >> 5;
    int i = blockIdx.x * SCAN_B + tid;
    int v = (i < N_NODES) ? g_deg[i] : 0;
    int s = v;
    #pragma unroll
    for (int ofs = 1; ofs < 32; ofs <<= 1) {
        int t = __shfl_up_sync(0xffffffff, s, ofs);
        if (lane >= ofs) s += t;
    }
    if (lane == 31) wsum[w] = s;
    __syncthreads();
    if (w == 0) {
        int ws = wsum[lane];
        #pragma unroll
        for (int ofs = 1; ofs < 32; ofs <<= 1) {
            int t = __shfl_up_sync(0xffffffff, ws, ofs);
            if (lane >= ofs) ws += t;
        }
        wsum[lane] = ws;   // inclusive warp sums
    }
    __syncthreads();
    int prefix = w ? wsum[w - 1] : 0;
    if (i < N_NODES) g_excl[i] = prefix + s - v;
    if (tid == 0) g_bsum[blockIdx.x] = wsum[31];
}

// ---- finish scan (per-block prefix of g_bsum) -----------------------------
__global__ __launch_bounds__(SCAN_B) void k_scan3() {
    __shared__ int s_add;
    int tid = threadIdx.x;
    int blk = blockIdx.x;

    if (tid < 32) {
        int acc = 0;
        for (int k = tid; k < blk; k += 32) acc += g_bsum[k];
        #pragma unroll
        for (int ofs = 16; ofs > 0; ofs >>= 1)
            acc += __shfl_down_sync(0xffffffff, acc, ofs);
        if (tid == 0) s_add = acc;
    }
    __syncthreads();
    int add = s_add;

    int i = blk * SCAN_B + tid;
    if (i < N_NODES) g_off[i] = g_excl[i] + add;
    if (i == 0) g_off[N_NODES] = N_EDGES;
}

// ---- place edges into CSR (no atomics, one packed read) -------------------
__global__ void k_place(const int* __restrict__ source) {
    int e = blockIdx.x * blockDim.x + threadIdx.x;
    if (e >= N_EDGES) return;
    int tp = g_tp[e];
    int t = tp & 0x1FFFF;
    int pos = tp >> 17;
    g_sorted_src[g_off[t] + pos] = source[e];
}

// ---------------------------------------------------------------------------
// Dense GEMM: Y[n,:] = fp16( inv[n] * (x[n,:] @ W) )  via tf32 wmma.
// 4 warps / 128 threads per block; all 8 A fragments preloaded (MLP=8 on the
// global-load path) before the register/smem-resident MMA loop.
// ---------------------------------------------------------------------------
#define GEMM_THREADS  128
#define GEMM_WARPS    4
#define ROWS_PER_BLK  (GEMM_WARPS * 16)    // 64
#define N_ROWTILES    (N_NODES / 16)       // 6250 (exact)
#define GEMM_BLOCKS   ((N_ROWTILES + GEMM_WARPS - 1) / GEMM_WARPS)   // 1563

__global__ __launch_bounds__(GEMM_THREADS) void k_gemm(
    const float* __restrict__ x,
    const float* __restrict__ W)
{
    __shared__ float sW[D_FEAT * UNITS];          // 16 KB
    __shared__ float sC[ROWS_PER_BLK * UNITS];    // 16 KB

    int tid = threadIdx.x;
    #pragma unroll
    for (int i = 0; i < (D_FEAT * UNITS) / GEMM_THREADS; i++)
        sW[tid + i * GEMM_THREADS] = W[tid + i * GEMM_THREADS];
    __syncthreads();

    int w = tid >> 5;
    int tile_row = blockIdx.x * GEMM_WARPS + w;
    if (tile_row < N_ROWTILES) {
        // preload all A fragments (8 independent global loads)
        wmma::fragment<wmma::matrix_a, 16, 16, 8,
                       wmma::precision::tf32, wmma::row_major> a[8];
        const float* abase = x + tile_row * 16 * D_FEAT;
        #pragma unroll
        for (int k = 0; k < 8; k++)
            wmma::load_matrix_sync(a[k], abase + k * 8, D_FEAT);
        #pragma unroll
        for (int k = 0; k < 8; k++)
            #pragma unroll
            for (int i = 0; i < a[k].num_elements; i++)
                a[k].x[i] = wmma::__float_to_tf32(a[k].x[i]);

        wmma::fragment<wmma::accumulator, 16, 16, 8, float> c[4];
        #pragma unroll
        for (int n = 0; n < 4; n++) wmma::fill_fragment(c[n], 0.f);

        #pragma unroll
        for (int k = 0; k < 8; k++) {
            #pragma unroll
            for (int n = 0; n < 4; n++) {
                wmma::fragment<wmma::matrix_b, 16, 16, 8,
                               wmma::precision::tf32, wmma::row_major> bf;
                wmma::load_matrix_sync(bf, sW + (k * 8) * UNITS + n * 16, UNITS);
                #pragma unroll
                for (int i = 0; i < bf.num_elements; i++)
                    bf.x[i] = wmma::__float_to_tf32(bf.x[i]);
                wmma::mma_sync(c[n], a[k], bf, c[n]);
            }
        }
        #pragma unroll
        for (int n = 0; n < 4; n++)
            wmma::store_matrix_sync(sC + (w * 16) * UNITS + n * 16, c[n],
                                    UNITS, wmma::mem_row_major);
    }
    __syncthreads();

    // epilogue: scale rows by inv, convert to fp16, store
    int base_row = blockIdx.x * ROWS_PER_BLK;
    __half2* y2 = (__half2*)g_y4;
    #pragma unroll
    for (int i = 0; i < (ROWS_PER_BLK * UNITS / 2) / GEMM_THREADS; i++) {
        int idx = tid + i * GEMM_THREADS;    // half2 slot in block tile
        int lr  = idx >> 5;                  // local row (32 half2 per row)
        int c2  = idx & 31;
        int row = base_row + lr;
        if (row < N_NODES) {
            float s = g_inv[row];
            float2 v;
            v.x = sC[lr * UNITS + c2 * 2]     * s;
            v.y = sC[lr * UNITS + c2 * 2 + 1] * s;
            y2[row * 32 + c2] = __float22half2_rn(v);
        }
    }
}

// ---------------------------------------------------------------------------
// Gather: out[n] = relu( inv[n] * sum_{s in row(n)} Y[s] + b )
// One node per warp; 4 octets interleave edges with stride 4; the single
// main loop keeps 4 independent LDG.128 per lane in flight.
// Also re-zeroes g_deg[n] for the next graph replay.
// ---------------------------------------------------------------------------
#define GATH_THREADS   256
#define NODES_PER_GBLK 8      // 8 warps * 1 node

__global__ __launch_bounds__(GATH_THREADS) void k_gather(
    const float* __restrict__ b,
    float* __restrict__ out)
{
    __shared__ float sB[UNITS];
    int tid  = threadIdx.x;
    int lane = tid & 31;
    int w    = tid >> 5;
    int q    = lane >> 3;    // octet id: which edge of a group of 4
    int fl   = lane & 7;     // uint4 slot within the 128-B row

    if (tid < UNITS) sB[tid] = b[tid];
    __syncthreads();

    int n = blockIdx.x * NODES_PER_GBLK + w;
    if (n >= N_NODES) return;

    int beg = g_off[n];
    int end = g_off[n + 1];
    float inv_t = g_inv[n];

    float2 a0 = make_float2(0.f, 0.f), a1 = a0, a2 = a0, a3 = a0;
    float2 b0 = a0, b1 = a0, b2 = a0, b3 = a0;

    for (int ee = beg + q; ee < end; ee += 16) {
        int e1 = ee + 4, e2 = ee + 8, e3 = ee + 12;
        int s0 = g_sorted_src[ee];
        int s1 = g_sorted_src[e1 < end ? e1 : ee];
        int s2 = g_sorted_src[e2 < end ? e2 : ee];
        int s3 = g_sorted_src[e3 < end ? e3 : ee];
        float f1 = (e1 < end) ? 1.f : 0.f;
        float f2 = (e2 < end) ? 1.f : 0.f;
        float f3 = (e3 < end) ? 1.f : 0.f;
        uint4 u0 = g_y4[s0 * 8 + fl];
        uint4 u1 = g_y4[s1 * 8 + fl];
        uint4 u2 = g_y4[s2 * 8 + fl];
        uint4 u3 = g_y4[s3 * 8 + fl];
        const __half2* h0 = (const __half2*)&u0;
        const __half2* h1 = (const __half2*)&u1;
        const __half2* h2 = (const __half2*)&u2;
        const __half2* h3 = (const __half2*)&u3;
        float2 f;
        f = __half22float2(h0[0]); a0.x += f.x;            a0.y += f.y;
        f = __half22float2(h0[1]); a1.x += f.x;            a1.y += f.y;
        f = __half22float2(h0[2]); a2.x += f.x;            a2.y += f.y;
        f = __half22float2(h0[3]); a3.x += f.x;            a3.y += f.y;
        f = __half22float2(h1[0]); b0.x = fmaf(f1, f.x, b0.x); b0.y = fmaf(f1, f.y, b0.y);
        f = __half22float2(h1[1]); b1.x = fmaf(f1, f.x, b1.x); b1.y = fmaf(f1, f.y, b1.y);
        f = __half22float2(h1[2]); b2.x = fmaf(f1, f.x, b2.x); b2.y = fmaf(f1, f.y, b2.y);
        f = __half22float2(h1[3]); b3.x = fmaf(f1, f.x, b3.x); b3.y = fmaf(f1, f.y, b3.y);
        f = __half22float2(h2[0]); a0.x = fmaf(f2, f.x, a0.x); a0.y = fmaf(f2, f.y, a0.y);
        f = __half22float2(h2[1]); a1.x = fmaf(f2, f.x, a1.x); a1.y = fmaf(f2, f.y, a1.y);
        f = __half22float2(h2[2]); a2.x = fmaf(f2, f.x, a2.x); a2.y = fmaf(f2, f.y, a2.y);
        f = __half22float2(h2[3]); a3.x = fmaf(f2, f.x, a3.x); a3.y = fmaf(f2, f.y, a3.y);
        f = __half22float2(h3[0]); b0.x = fmaf(f3, f.x, b0.x); b0.y = fmaf(f3, f.y, b0.y);
        f = __half22float2(h3[1]); b1.x = fmaf(f3, f.x, b1.x); b1.y = fmaf(f3, f.y, b1.y);
        f = __half22float2(h3[2]); b2.x = fmaf(f3, f.x, b2.x); b2.y = fmaf(f3, f.y, b2.y);
        f = __half22float2(h3[3]); b3.x = fmaf(f3, f.x, b3.x); b3.y = fmaf(f3, f.y, b3.y);
    }

    a0.x += b0.x; a0.y += b0.y;  a1.x += b1.x; a1.y += b1.y;
    a2.x += b2.x; a2.y += b2.y;  a3.x += b3.x; a3.y += b3.y;

    // combine octets: lanes 0-7 end with full sums for cols fl*8..+7
    #pragma unroll
    for (int ofs = 16; ofs >= 8; ofs >>= 1) {
        a0.x += __shfl_down_sync(0xffffffff, a0.x, ofs);
        a0.y += __shfl_down_sync(0xffffffff, a0.y, ofs);
        a1.x += __shfl_down_sync(0xffffffff, a1.x, ofs);
        a1.y += __shfl_down_sync(0xffffffff, a1.y, ofs);
        a2.x += __shfl_down_sync(0xffffffff, a2.x, ofs);
        a2.y += __shfl_down_sync(0xffffffff, a2.y, ofs);
        a3.x += __shfl_down_sync(0xffffffff, a3.x, ofs);
        a3.y += __shfl_down_sync(0xffffffff, a3.y, ofs);
    }
    if (q == 0) {
        int cb = fl * 8;
        float4 o0, o1;
        o0.x = fmaxf(fmaf(inv_t, a0.x, sB[cb + 0]), 0.f);
        o0.y = fmaxf(fmaf(inv_t, a0.y, sB[cb + 1]), 0.f);
        o0.z = fmaxf(fmaf(inv_t, a1.x, sB[cb + 2]), 0.f);
        o0.w = fmaxf(fmaf(inv_t, a1.y, sB[cb + 3]), 0.f);
        o1.x = fmaxf(fmaf(inv_t, a2.x, sB[cb + 4]), 0.f);
        o1.y = fmaxf(fmaf(inv_t, a2.y, sB[cb + 5]), 0.f);
        o1.z = fmaxf(fmaf(inv_t, a3.x, sB[cb + 6]), 0.f);
        o1.w = fmaxf(fmaf(inv_t, a3.y, sB[cb + 7]), 0.f);
        float4* out4 = (float4*)(out + n * UNITS);
        out4[fl * 2]     = o0;
        out4[fl * 2 + 1] = o1;
    }
    if (lane == 0) g_deg[n] = 0;   // reset for next replay
}

// ---------------------------------------------------------------------------
extern "C" void kernel_launch(void* const* d_in, const int* in_sizes, int n_in,
                              void* d_out, int out_size) {
    const float* x      = (const float*)d_in[0];
    const float* W      = (const float*)d_in[1];
    const float* b      = (const float*)d_in[2];
    const int*   source = (const int*)d_in[3];
    const int*   target = (const int*)d_in[4];
    float* out = (float*)d_out;

    static cudaStream_t s1 = nullptr;
    static cudaEvent_t evA = nullptr, evB = nullptr;
    if (s1 == nullptr) {
        cudaStreamCreateWithFlags(&s1, cudaStreamNonBlocking);
        cudaEventCreateWithFlags(&evA, cudaEventDisableTiming);
        cudaEventCreateWithFlags(&evB, cudaEventDisableTiming);
    }

    const int T = 256;
    k_degree<<<(N_EDGES + T - 1) / T, T>>>(target);
    k_inv<<<(N_NODES + T - 1) / T, T>>>();

    // fork: gemm (needs only g_inv) overlaps scan1+scan3+place
    cudaEventRecord(evA, 0);
    cudaStreamWaitEvent(s1, evA, 0);
    k_gemm<<<GEMM_BLOCKS, GEMM_THREADS, 0, s1>>>(x, W);
    cudaEventRecord(evB, s1);

    k_scan1<<<N_SCANB, SCAN_B>>>();
    k_scan3<<<N_SCANB, SCAN_B>>>();
    k_place<<<(N_EDGES + T - 1) / T, T>>>(source);

    // join: gather needs both place (stream 0) and gemm (s1)
    cudaStreamWaitEvent(0, evB, 0);
    k_gather<<<(N_NODES + NODES_PER_GBLK - 1) / NODES_PER_GBLK, GATH_THREADS>>>(b, out);
}

// round 15
// speedup vs baseline: 1.3730x; 1.0217x over previous
#include <cuda_runtime.h>
#include <cuda_fp16.h>
#include <cuda_bf16.h>
#include <mma.h>

using namespace nvcuda;

#define N_NODES 100000
#define N_EDGES 1600000
#define D_FEAT  64
#define UNITS   64
#define SCAN_B  1024
#define N_SCANB ((N_NODES + SCAN_B - 1) / SCAN_B)   // 98

// ---- scratch (__device__ globals; no allocations allowed) -----------------
__device__ int    g_deg[N_NODES];            // zeroed by k_gather of prior call
__device__ int    g_excl[N_NODES];
__device__ int    g_off[N_NODES + 1];
__device__ int    g_bsum[128];
__device__ float  g_inv[N_NODES];
__device__ int    g_tp[N_EDGES];             // packed (pos<<17)|target
__device__ int    g_sorted_src[N_EDGES];
__device__ uint4  g_y4[N_NODES * 8];         // fp16 Y = (inv*x)@W : 128 B/node

// ---------------------------------------------------------------------------
// degree + per-edge rank in one atomic pass (g_deg is 0 on entry)
__global__ void k_degree(const int* __restrict__ target) {
    int e = blockIdx.x * blockDim.x + threadIdx.x;
    if (e < N_EDGES) {
        int t = target[e];
        int pos = atomicAdd(&g_deg[t], 1);
        g_tp[e] = (pos << 17) | t;
    }
}

// ---- block-local exclusive scan of degrees (shfl) + inv -------------------
__global__ __launch_bounds__(SCAN_B) void k_scan1() {
    __shared__ int wsum[32];
    int tid = threadIdx.x;
    int lane = tid & 31;
    int w = tid >> 5;
    int i = blockIdx.x * SCAN_B + tid;
    int v = (i < N_NODES) ? g_deg[i] : 0;
    if (i < N_NODES) g_inv[i] = rsqrtf((float)v);
    int s = v;
    #pragma unroll
    for (int ofs = 1; ofs < 32; ofs <<= 1) {
        int t = __shfl_up_sync(0xffffffff, s, ofs);
        if (lane >= ofs) s += t;
    }
    if (lane == 31) wsum[w] = s;
    __syncthreads();
    if (w == 0) {
        int ws = wsum[lane];
        #pragma unroll
        for (int ofs = 1; ofs < 32; ofs <<= 1) {
            int t = __shfl_up_sync(0xffffffff, ws, ofs);
            if (lane >= ofs) ws += t;
        }
        wsum[lane] = ws;   // inclusive warp sums
    }
    __syncthreads();
    int prefix = w ? wsum[w - 1] : 0;
    if (i < N_NODES) g_excl[i] = prefix + s - v;
    if (tid == 0) g_bsum[blockIdx.x] = wsum[31];
}

// ---- finish scan (per-block prefix of g_bsum) -----------------------------
__global__ __launch_bounds__(SCAN_B) void k_scan3() {
    __shared__ int s_add;
    int tid = threadIdx.x;
    int blk = blockIdx.x;

    if (tid < 32) {
        int acc = 0;
        for (int k = tid; k < blk; k += 32) acc += g_bsum[k];
        #pragma unroll
        for (int ofs = 16; ofs > 0; ofs >>= 1)
            acc += __shfl_down_sync(0xffffffff, acc, ofs);
        if (tid == 0) s_add = acc;
    }
    __syncthreads();
    int add = s_add;

    int i = blk * SCAN_B + tid;
    if (i < N_NODES) g_off[i] = g_excl[i] + add;
    if (i == 0) g_off[N_NODES] = N_EDGES;
}

// ---- place edges into CSR (no atomics, one packed read) -------------------
__global__ void k_place(const int* __restrict__ source) {
    int e = blockIdx.x * blockDim.x + threadIdx.x;
    if (e >= N_EDGES) return;
    int tp = g_tp[e];
    int t = tp & 0x1FFFF;
    int pos = tp >> 17;
    g_sorted_src[g_off[t] + pos] = source[e];
}

// ---------------------------------------------------------------------------
// Dense GEMM: Y[n,:] = fp16( inv[n] * (x[n,:] @ W) )  via tf32 wmma.
// ---------------------------------------------------------------------------
#define GEMM_THREADS  128
#define GEMM_WARPS    4
#define ROWS_PER_BLK  (GEMM_WARPS * 16)    // 64
#define N_ROWTILES    (N_NODES / 16)       // 6250 (exact)
#define GEMM_BLOCKS   ((N_ROWTILES + GEMM_WARPS - 1) / GEMM_WARPS)   // 1563

__global__ __launch_bounds__(GEMM_THREADS) void k_gemm(
    const float* __restrict__ x,
    const float* __restrict__ W)
{
    __shared__ float sW[D_FEAT * UNITS];          // 16 KB
    __shared__ float sC[ROWS_PER_BLK * UNITS];    // 16 KB

    int tid = threadIdx.x;
    #pragma unroll
    for (int i = 0; i < (D_FEAT * UNITS) / GEMM_THREADS; i++)
        sW[tid + i * GEMM_THREADS] = W[tid + i * GEMM_THREADS];
    __syncthreads();

    int w = tid >> 5;
    int tile_row = blockIdx.x * GEMM_WARPS + w;
    if (tile_row < N_ROWTILES) {
        wmma::fragment<wmma::matrix_a, 16, 16, 8,
                       wmma::precision::tf32, wmma::row_major> a[8];
        const float* abase = x + tile_row * 16 * D_FEAT;
        #pragma unroll
        for (int k = 0; k < 8; k++)
            wmma::load_matrix_sync(a[k], abase + k * 8, D_FEAT);
        #pragma unroll
        for (int k = 0; k < 8; k++)
            #pragma unroll
            for (int i = 0; i < a[k].num_elements; i++)
                a[k].x[i] = wmma::__float_to_tf32(a[k].x[i]);

        wmma::fragment<wmma::accumulator, 16, 16, 8, float> c[4];
        #pragma unroll
        for (int n = 0; n < 4; n++) wmma::fill_fragment(c[n], 0.f);

        #pragma unroll
        for (int k = 0; k < 8; k++) {
            #pragma unroll
            for (int n = 0; n < 4; n++) {
                wmma::fragment<wmma::matrix_b, 16, 16, 8,
                               wmma::precision::tf32, wmma::row_major> bf;
                wmma::load_matrix_sync(bf, sW + (k * 8) * UNITS + n * 16, UNITS);
                #pragma unroll
                for (int i = 0; i < bf.num_elements; i++)
                    bf.x[i] = wmma::__float_to_tf32(bf.x[i]);
                wmma::mma_sync(c[n], a[k], bf, c[n]);
            }
        }
        #pragma unroll
        for (int n = 0; n < 4; n++)
            wmma::store_matrix_sync(sC + (w * 16) * UNITS + n * 16, c[n],
                                    UNITS, wmma::mem_row_major);
    }
    __syncthreads();

    int base_row = blockIdx.x * ROWS_PER_BLK;
    __half2* y2 = (__half2*)g_y4;
    #pragma unroll
    for (int i = 0; i < (ROWS_PER_BLK * UNITS / 2) / GEMM_THREADS; i++) {
        int idx = tid + i * GEMM_THREADS;
        int lr  = idx >> 5;
        int c2  = idx & 31;
        int row = base_row + lr;
        if (row < N_NODES) {
            float s = g_inv[row];
            float2 v;
            v.x = sC[lr * UNITS + c2 * 2]     * s;
            v.y = sC[lr * UNITS + c2 * 2 + 1] * s;
            y2[row * 32 + c2] = __float22half2_rn(v);
        }
    }
}

// ---------------------------------------------------------------------------
// Gather: out[n] = relu( inv[n] * sum_{s in row(n)} Y[s] + b )
// ONE OCTET (8 lanes) per node: the octet walks all edges of its node with a
// 4-deep MLP loop into 4 accumulator banks; fold in registers; write the 8
// output floats directly. No shuffles, no cross-octet reduction.
// Also re-zeroes g_deg[n] for the next graph replay.
// ---------------------------------------------------------------------------
#define GATH_THREADS   256
#define NODES_PER_GBLK 32     // 32 octets per block

__global__ __launch_bounds__(GATH_THREADS) void k_gather(
    const float* __restrict__ b,
    float* __restrict__ out)
{
    __shared__ float sB[UNITS];
    int tid = threadIdx.x;
    if (tid < UNITS) sB[tid] = b[tid];
    __syncthreads();

    int fl  = tid & 7;          // uint4 slot within the 128-B row
    int oct = tid >> 3;         // octet id within block
    int n = blockIdx.x * NODES_PER_GBLK + oct;
    if (n >= N_NODES) return;

    int beg = g_off[n];
    int end = g_off[n + 1];
    float inv_t = g_inv[n];

    // 4 accumulator banks (one per edge slot), 4 float2 each
    float2 A0 = make_float2(0.f, 0.f), A1 = A0, A2 = A0, A3 = A0;
    float2 B0 = A0, B1 = A0, B2 = A0, B3 = A0;
    float2 C0 = A0, C1 = A0, C2 = A0, C3 = A0;
    float2 D0 = A0, D1 = A0, D2 = A0, D3 = A0;

    for (int ee = beg; ee < end; ee += 4) {
        int e1 = ee + 1, e2 = ee + 2, e3 = ee + 3;
        int s0 = g_sorted_src[ee];
        int s1 = g_sorted_src[e1 < end ? e1 : ee];
        int s2 = g_sorted_src[e2 < end ? e2 : ee];
        int s3 = g_sorted_src[e3 < end ? e3 : ee];
        float f1 = (e1 < end) ? 1.f : 0.f;
        float f2 = (e2 < end) ? 1.f : 0.f;
        float f3 = (e3 < end) ? 1.f : 0.f;
        uint4 u0 = g_y4[s0 * 8 + fl];
        uint4 u1 = g_y4[s1 * 8 + fl];
        uint4 u2 = g_y4[s2 * 8 + fl];
        uint4 u3 = g_y4[s3 * 8 + fl];
        const __half2* h0 = (const __half2*)&u0;
        const __half2* h1 = (const __half2*)&u1;
        const __half2* h2 = (const __half2*)&u2;
        const __half2* h3 = (const __half2*)&u3;
        float2 f;
        f = __half22float2(h0[0]); A0.x += f.x;              A0.y += f.y;
        f = __half22float2(h0[1]); A1.x += f.x;              A1.y += f.y;
        f = __half22float2(h0[2]); A2.x += f.x;              A2.y += f.y;
        f = __half22float2(h0[3]); A3.x += f.x;              A3.y += f.y;
        f = __half22float2(h1[0]); B0.x = fmaf(f1, f.x, B0.x); B0.y = fmaf(f1, f.y, B0.y);
        f = __half22float2(h1[1]); B1.x = fmaf(f1, f.x, B1.x); B1.y = fmaf(f1, f.y, B1.y);
        f = __half22float2(h1[2]); B2.x = fmaf(f1, f.x, B2.x); B2.y = fmaf(f1, f.y, B2.y);
        f = __half22float2(h1[3]); B3.x = fmaf(f1, f.x, B3.x); B3.y = fmaf(f1, f.y, B3.y);
        f = __half22float2(h2[0]); C0.x = fmaf(f2, f.x, C0.x); C0.y = fmaf(f2, f.y, C0.y);
        f = __half22float2(h2[1]); C1.x = fmaf(f2, f.x, C1.x); C1.y = fmaf(f2, f.y, C1.y);
        f = __half22float2(h2[2]); C2.x = fmaf(f2, f.x, C2.x); C2.y = fmaf(f2, f.y, C2.y);
        f = __half22float2(h2[3]); C3.x = fmaf(f2, f.x, C3.x); C3.y = fmaf(f2, f.y, C3.y);
        f = __half22float2(h3[0]); D0.x = fmaf(f3, f.x, D0.x); D0.y = fmaf(f3, f.y, D0.y);
        f = __half22float2(h3[1]); D1.x = fmaf(f3, f.x, D1.x); D1.y = fmaf(f3, f.y, D1.y);
        f = __half22float2(h3[2]); D2.x = fmaf(f3, f.x, D2.x); D2.y = fmaf(f3, f.y, D2.y);
        f = __half22float2(h3[3]); D3.x = fmaf(f3, f.x, D3.x); D3.y = fmaf(f3, f.y, D3.y);
    }

    // fold banks
    A0.x += B0.x + C0.x + D0.x;  A0.y += B0.y + C0.y + D0.y;
    A1.x += B1.x + C1.x + D1.x;  A1.y += B1.y + C1.y + D1.y;
    A2.x += B2.x + C2.x + D2.x;  A2.y += B2.y + C2.y + D2.y;
    A3.x += B3.x + C3.x + D3.x;  A3.y += B3.y + C3.y + D3.y;

    int cb = fl * 8;
    float4 o0, o1;
    o0.x = fmaxf(fmaf(inv_t, A0.x, sB[cb + 0]), 0.f);
    o0.y = fmaxf(fmaf(inv_t, A0.y, sB[cb + 1]), 0.f);
    o0.z = fmaxf(fmaf(inv_t, A1.x, sB[cb + 2]), 0.f);
    o0.w = fmaxf(fmaf(inv_t, A1.y, sB[cb + 3]), 0.f);
    o1.x = fmaxf(fmaf(inv_t, A2.x, sB[cb + 4]), 0.f);
    o1.y = fmaxf(fmaf(inv_t, A2.y, sB[cb + 5]), 0.f);
    o1.z = fmaxf(fmaf(inv_t, A3.x, sB[cb + 6]), 0.f);
    o1.w = fmaxf(fmaf(inv_t, A3.y, sB[cb + 7]), 0.f);
    float4* out4 = (float4*)(out + n * UNITS);
    out4[fl * 2]     = o0;
    out4[fl * 2 + 1] = o1;

    if (fl == 0) g_deg[n] = 0;   // reset for next replay
}

// ---------------------------------------------------------------------------
extern "C" void kernel_launch(void* const* d_in, const int* in_sizes, int n_in,
                              void* d_out, int out_size) {
    const float* x      = (const float*)d_in[0];
    const float* W      = (const float*)d_in[1];
    const float* b      = (const float*)d_in[2];
    const int*   source = (const int*)d_in[3];
    const int*   target = (const int*)d_in[4];
    float* out = (float*)d_out;

    static cudaStream_t s1 = nullptr;
    static cudaEvent_t evA = nullptr, evB = nullptr;
    if (s1 == nullptr) {
        cudaStreamCreateWithFlags(&s1, cudaStreamNonBlocking);
        cudaEventCreateWithFlags(&evA, cudaEventDisableTiming);
        cudaEventCreateWithFlags(&evB, cudaEventDisableTiming);
    }

    const int T = 256;
    k_degree<<<(N_EDGES + T - 1) / T, T>>>(target);
    k_scan1<<<N_SCANB, SCAN_B>>>();     // also computes g_inv

    // fork: gemm (needs only g_inv) overlaps scan3+place
    cudaEventRecord(evA, 0);
    cudaStreamWaitEvent(s1, evA, 0);
    k_gemm<<<GEMM_BLOCKS, GEMM_THREADS, 0, s1>>>(x, W);
    cudaEventRecord(evB, s1);

    k_scan3<<<N_SCANB, SCAN_B>>>();
    k_place<<<(N_EDGES + T - 1) / T, T>>>(source);

    // join: gather needs both place (stream 0) and gemm (s1)
    cudaStreamWaitEvent(0, evB, 0);
    k_gather<<<(N_NODES + NODES_PER_GBLK - 1) / NODES_PER_GBLK, GATH_THREADS>>>(b, out);
}

// round 16
// speedup vs baseline: 1.4118x; 1.0282x over previous
#include <cuda_runtime.h>
#include <cuda_fp16.h>
#include <cuda_bf16.h>
#include <mma.h>

using namespace nvcuda;

#define N_NODES 100000
#define N_EDGES 1600000
#define D_FEAT  64
#define UNITS   64
#define SCAN_B  1024
#define N_SCANB ((N_NODES + SCAN_B - 1) / SCAN_B)   // 98

// ---- scratch (__device__ globals; no allocations allowed) -----------------
__device__ int    g_deg[N_NODES];            // zeroed by k_gather of prior call
__device__ int    g_excl[N_NODES];           // exclusive scan within scan-block
__device__ int    g_bsum[128];               // per-scan-block degree sums
__device__ int    g_tp[N_EDGES];             // packed (pos<<17)|target
__device__ int    g_sorted_src[N_EDGES];
__device__ uint4  g_y4[N_NODES * 8];         // fp16 Y = (inv*x)@W : 128 B/node

// ---------------------------------------------------------------------------
// degree + per-edge rank in one atomic pass (g_deg is 0 on entry)
__global__ void k_degree(const int* __restrict__ target) {
    int e = blockIdx.x * blockDim.x + threadIdx.x;
    if (e < N_EDGES) {
        int t = target[e];
        int pos = atomicAdd(&g_deg[t], 1);
        g_tp[e] = (pos << 17) | t;
    }
}

// ---- block-local exclusive scan of degrees (shfl) -------------------------
__global__ __launch_bounds__(SCAN_B) void k_scan1() {
    __shared__ int wsum[32];
    int tid = threadIdx.x;
    int lane = tid & 31;
    int w = tid >> 5;
    int i = blockIdx.x * SCAN_B + tid;
    int v = (i < N_NODES) ? g_deg[i] : 0;
    int s = v;
    #pragma unroll
    for (int ofs = 1; ofs < 32; ofs <<= 1) {
        int t = __shfl_up_sync(0xffffffff, s, ofs);
        if (lane >= ofs) s += t;
    }
    if (lane == 31) wsum[w] = s;
    __syncthreads();
    if (w == 0) {
        int ws = wsum[lane];
        #pragma unroll
        for (int ofs = 1; ofs < 32; ofs <<= 1) {
            int t = __shfl_up_sync(0xffffffff, ws, ofs);
            if (lane >= ofs) ws += t;
        }
        wsum[lane] = ws;   // inclusive warp sums
    }
    __syncthreads();
    int prefix = w ? wsum[w - 1] : 0;
    if (i < N_NODES) g_excl[i] = prefix + s - v;
    if (tid == 0) g_bsum[blockIdx.x] = wsum[31];
}

// ---- place edges into CSR; block-prefix of g_bsum computed in shared ------
__global__ void k_place(const int* __restrict__ source) {
    __shared__ int sboff[128];
    int tid = threadIdx.x;
    if (tid < 32) {
        int carry = 0;
        #pragma unroll
        for (int base = 0; base < 128; base += 32) {
            int idx = base + tid;
            int v = (idx < N_SCANB) ? g_bsum[idx] : 0;
            int s = v;
            #pragma unroll
            for (int o = 1; o < 32; o <<= 1) {
                int t = __shfl_up_sync(0xffffffff, s, o);
                if (tid >= o) s += t;
            }
            sboff[idx] = carry + s - v;   // exclusive global prefix
            carry += __shfl_sync(0xffffffff, s, 31);
        }
    }
    __syncthreads();
    int e = blockIdx.x * blockDim.x + tid;
    if (e >= N_EDGES) return;
    int tp = g_tp[e];
    int t = tp & 0x1FFFF;
    int pos = tp >> 17;
    g_sorted_src[g_excl[t] + sboff[t >> 10] + pos] = source[e];
}

// ---------------------------------------------------------------------------
// Dense GEMM: Y[n,:] = fp16( rsqrt(deg[n]) * (x[n,:] @ W) )  via tf32 wmma.
// Forked right after k_degree (needs only g_deg).
// ---------------------------------------------------------------------------
#define GEMM_THREADS  128
#define GEMM_WARPS    4
#define ROWS_PER_BLK  (GEMM_WARPS * 16)    // 64
#define N_ROWTILES    (N_NODES / 16)       // 6250 (exact)
#define GEMM_BLOCKS   ((N_ROWTILES + GEMM_WARPS - 1) / GEMM_WARPS)   // 1563

__global__ __launch_bounds__(GEMM_THREADS) void k_gemm(
    const float* __restrict__ x,
    const float* __restrict__ W)
{
    __shared__ float sW[D_FEAT * UNITS];          // 16 KB
    __shared__ float sC[ROWS_PER_BLK * UNITS];    // 16 KB

    int tid = threadIdx.x;
    #pragma unroll
    for (int i = 0; i < (D_FEAT * UNITS) / GEMM_THREADS; i++)
        sW[tid + i * GEMM_THREADS] = W[tid + i * GEMM_THREADS];
    __syncthreads();

    int w = tid >> 5;
    int tile_row = blockIdx.x * GEMM_WARPS + w;
    if (tile_row < N_ROWTILES) {
        wmma::fragment<wmma::matrix_a, 16, 16, 8,
                       wmma::precision::tf32, wmma::row_major> a[8];
        const float* abase = x + tile_row * 16 * D_FEAT;
        #pragma unroll
        for (int k = 0; k < 8; k++)
            wmma::load_matrix_sync(a[k], abase + k * 8, D_FEAT);
        #pragma unroll
        for (int k = 0; k < 8; k++)
            #pragma unroll
            for (int i = 0; i < a[k].num_elements; i++)
                a[k].x[i] = wmma::__float_to_tf32(a[k].x[i]);

        wmma::fragment<wmma::accumulator, 16, 16, 8, float> c[4];
        #pragma unroll
        for (int n = 0; n < 4; n++) wmma::fill_fragment(c[n], 0.f);

        #pragma unroll
        for (int k = 0; k < 8; k++) {
            #pragma unroll
            for (int n = 0; n < 4; n++) {
                wmma::fragment<wmma::matrix_b, 16, 16, 8,
                               wmma::precision::tf32, wmma::row_major> bf;
                wmma::load_matrix_sync(bf, sW + (k * 8) * UNITS + n * 16, UNITS);
                #pragma unroll
                for (int i = 0; i < bf.num_elements; i++)
                    bf.x[i] = wmma::__float_to_tf32(bf.x[i]);
                wmma::mma_sync(c[n], a[k], bf, c[n]);
            }
        }
        #pragma unroll
        for (int n = 0; n < 4; n++)
            wmma::store_matrix_sync(sC + (w * 16) * UNITS + n * 16, c[n],
                                    UNITS, wmma::mem_row_major);
    }
    __syncthreads();

    int base_row = blockIdx.x * ROWS_PER_BLK;
    __half2* y2 = (__half2*)g_y4;
    #pragma unroll
    for (int i = 0; i < (ROWS_PER_BLK * UNITS / 2) / GEMM_THREADS; i++) {
        int idx = tid + i * GEMM_THREADS;
        int lr  = idx >> 5;
        int c2  = idx & 31;
        int row = base_row + lr;
        if (row < N_NODES) {
            float s = rsqrtf((float)g_deg[row]);
            float2 v;
            v.x = sC[lr * UNITS + c2 * 2]     * s;
            v.y = sC[lr * UNITS + c2 * 2 + 1] * s;
            y2[row * 32 + c2] = __float22half2_rn(v);
        }
    }
}

// ---------------------------------------------------------------------------
// Gather: out[n] = relu( rsqrt(deg[n]) * sum_{s in row(n)} Y[s] + b )
// One octet per node; software-pipelined: next iteration's 4 source indices
// are prefetched while the current rows are in flight. beg from
// g_excl + block prefix (one value per gather block); end = beg + deg.
// Also re-zeroes g_deg[n] for the next graph replay.
// ---------------------------------------------------------------------------
#define GATH_THREADS   256
#define NODES_PER_GBLK 32     // 32 octets per block; 32 | 1024 so one scan-block

__global__ __launch_bounds__(GATH_THREADS) void k_gather(
    const float* __restrict__ b,
    float* __restrict__ out)
{
    __shared__ float sB[UNITS];
    __shared__ int s_add;
    int tid = threadIdx.x;
    if (tid < 32) {
        int blk = blockIdx.x >> 5;     // scan-block of this gather block
        int acc = 0;
        for (int k = tid; k < blk; k += 32) acc += g_bsum[k];
        #pragma unroll
        for (int ofs = 16; ofs > 0; ofs >>= 1)
            acc += __shfl_down_sync(0xffffffff, acc, ofs);
        if (tid == 0) s_add = acc;
    }
    if (tid < UNITS) sB[tid] = b[tid];
    __syncthreads();

    int fl  = tid & 7;          // uint4 slot within the 128-B row
    int oct = tid >> 3;         // octet id within block
    int n = blockIdx.x * NODES_PER_GBLK + oct;
    if (n >= N_NODES) return;

    int deg = g_deg[n];
    int beg = g_excl[n] + s_add;
    int end = beg + deg;
    float inv_t = rsqrtf((float)deg);

    float2 A0 = make_float2(0.f, 0.f), A1 = A0, A2 = A0, A3 = A0;
    float2 B0 = A0, B1 = A0, B2 = A0, B3 = A0;
    float2 C0 = A0, C1 = A0, C2 = A0, C3 = A0;
    float2 D0 = A0, D1 = A0, D2 = A0, D3 = A0;

    // prime the index pipeline
    int s0 = 0, s1 = 0, s2 = 0, s3 = 0;
    float f1 = 0.f, f2 = 0.f, f3 = 0.f;
    if (beg < end) {
        int e1 = beg + 1, e2 = beg + 2, e3 = beg + 3;
        s0 = g_sorted_src[beg];
        s1 = g_sorted_src[e1 < end ? e1 : beg];
        s2 = g_sorted_src[e2 < end ? e2 : beg];
        s3 = g_sorted_src[e3 < end ? e3 : beg];
        f1 = (e1 < end) ? 1.f : 0.f;
        f2 = (e2 < end) ? 1.f : 0.f;
        f3 = (e3 < end) ? 1.f : 0.f;
    }

    for (int ee = beg; ee < end; ) {
        // rows for current indices (indices already resident)
        uint4 u0 = g_y4[s0 * 8 + fl];
        uint4 u1 = g_y4[s1 * 8 + fl];
        uint4 u2 = g_y4[s2 * 8 + fl];
        uint4 u3 = g_y4[s3 * 8 + fl];

        // prefetch next iteration's indices while rows are in flight
        int ne = ee + 4;
        int t0 = 0, t1 = 0, t2 = 0, t3 = 0;
        float g1 = 0.f, g2 = 0.f, g3 = 0.f;
        if (ne < end) {
            int e1 = ne + 1, e2 = ne + 2, e3 = ne + 3;
            t0 = g_sorted_src[ne];
            t1 = g_sorted_src[e1 < end ? e1 : ne];
            t2 = g_sorted_src[e2 < end ? e2 : ne];
            t3 = g_sorted_src[e3 < end ? e3 : ne];
            g1 = (e1 < end) ? 1.f : 0.f;
            g2 = (e2 < end) ? 1.f : 0.f;
            g3 = (e3 < end) ? 1.f : 0.f;
        }

        const __half2* h0 = (const __half2*)&u0;
        const __half2* h1 = (const __half2*)&u1;
        const __half2* h2 = (const __half2*)&u2;
        const __half2* h3 = (const __half2*)&u3;
        float2 f;
        f = __half22float2(h0[0]); A0.x += f.x;              A0.y += f.y;
        f = __half22float2(h0[1]); A1.x += f.x;              A1.y += f.y;
        f = __half22float2(h0[2]); A2.x += f.x;              A2.y += f.y;
        f = __half22float2(h0[3]); A3.x += f.x;              A3.y += f.y;
        f = __half22float2(h1[0]); B0.x = fmaf(f1, f.x, B0.x); B0.y = fmaf(f1, f.y, B0.y);
        f = __half22float2(h1[1]); B1.x = fmaf(f1, f.x, B1.x); B1.y = fmaf(f1, f.y, B1.y);
        f = __half22float2(h1[2]); B2.x = fmaf(f1, f.x, B2.x); B2.y = fmaf(f1, f.y, B2.y);
        f = __half22float2(h1[3]); B3.x = fmaf(f1, f.x, B3.x); B3.y = fmaf(f1, f.y, B3.y);
        f = __half22float2(h2[0]); C0.x = fmaf(f2, f.x, C0.x); C0.y = fmaf(f2, f.y, C0.y);
        f = __half22float2(h2[1]); C1.x = fmaf(f2, f.x, C1.x); C1.y = fmaf(f2, f.y, C1.y);
        f = __half22float2(h2[2]); C2.x = fmaf(f2, f.x, C2.x); C2.y = fmaf(f2, f.y, C2.y);
        f = __half22float2(h2[3]); C3.x = fmaf(f2, f.x, C3.x); C3.y = fmaf(f2, f.y, C3.y);
        f = __half22float2(h3[0]); D0.x = fmaf(f3, f.x, D0.x); D0.y = fmaf(f3, f.y, D0.y);
        f = __half22float2(h3[1]); D1.x = fmaf(f3, f.x, D1.x); D1.y = fmaf(f3, f.y, D1.y);
        f = __half22float2(h3[2]); D2.x = fmaf(f3, f.x, D2.x); D2.y = fmaf(f3, f.y, D2.y);
        f = __half22float2(h3[3]); D3.x = fmaf(f3, f.x, D3.x); D3.y = fmaf(f3, f.y, D3.y);

        ee = ne;
        s0 = t0; s1 = t1; s2 = t2; s3 = t3;
        f1 = g1; f2 = g2; f3 = g3;
    }

    // fold banks
    A0.x += B0.x + C0.x + D0.x;  A0.y += B0.y + C0.y + D0.y;
    A1.x += B1.x + C1.x + D1.x;  A1.y += B1.y + C1.y + D1.y;
    A2.x += B2.x + C2.x + D2.x;  A2.y += B2.y + C2.y + D2.y;
    A3.x += B3.x + C3.x + D3.x;  A3.y += B3.y + C3.y + D3.y;

    int cb = fl * 8;
    float4 o0, o1;
    o0.x = fmaxf(fmaf(inv_t, A0.x, sB[cb + 0]), 0.f);
    o0.y = fmaxf(fmaf(inv_t, A0.y, sB[cb + 1]), 0.f);
    o0.z = fmaxf(fmaf(inv_t, A1.x, sB[cb + 2]), 0.f);
    o0.w = fmaxf(fmaf(inv_t, A1.y, sB[cb + 3]), 0.f);
    o1.x = fmaxf(fmaf(inv_t, A2.x, sB[cb + 4]), 0.f);
    o1.y = fmaxf(fmaf(inv_t, A2.y, sB[cb + 5]), 0.f);
    o1.z = fmaxf(fmaf(inv_t, A3.x, sB[cb + 6]), 0.f);
    o1.w = fmaxf(fmaf(inv_t, A3.y, sB[cb + 7]), 0.f);
    float4* out4 = (float4*)(out + n * UNITS);
    out4[fl * 2]     = o0;
    out4[fl * 2 + 1] = o1;

    if (fl == 0) g_deg[n] = 0;   // reset for next replay
}

// ---------------------------------------------------------------------------
extern "C" void kernel_launch(void* const* d_in, const int* in_sizes, int n_in,
                              void* d_out, int out_size) {
    const float* x      = (const float*)d_in[0];
    const float* W      = (const float*)d_in[1];
    const float* b      = (const float*)d_in[2];
    const int*   source = (const int*)d_in[3];
    const int*   target = (const int*)d_in[4];
    float* out = (float*)d_out;

    static cudaStream_t s1 = nullptr;
    static cudaEvent_t evA = nullptr, evB = nullptr;
    if (s1 == nullptr) {
        cudaStreamCreateWithFlags(&s1, cudaStreamNonBlocking);
        cudaEventCreateWithFlags(&evA, cudaEventDisableTiming);
        cudaEventCreateWithFlags(&evB, cudaEventDisableTiming);
    }

    const int T = 256;
    k_degree<<<(N_EDGES + T - 1) / T, T>>>(target);

    // fork: gemm needs only g_deg (computes rsqrt inline) — overlaps scan1+place
    cudaEventRecord(evA, 0);
    cudaStreamWaitEvent(s1, evA, 0);
    k_gemm<<<GEMM_BLOCKS, GEMM_THREADS, 0, s1>>>(x, W);
    cudaEventRecord(evB, s1);

    k_scan1<<<N_SCANB, SCAN_B>>>();
    k_place<<<(N_EDGES + T - 1) / T, T>>>(source);

    // join: gather needs place (stream 0) and gemm (s1)
    cudaStreamWaitEvent(0, evB, 0);
    k_gather<<<(N_NODES + NODES_PER_GBLK - 1) / NODES_PER_GBLK, GATH_THREADS>>>(b, out);
}